// round 12
// baseline (speedup 1.0000x reference)
#include <cuda_runtime.h>
#include <math.h>
#include <stdint.h>

// ---------------- problem constants ----------------
#define NLVL   12
#define TBL    (1u << 19)
#define TMASK  (TBL - 1u)
#define EMBD   24
#define DOUT   257
#define TPB    256
#define TILE_P 256

#define PRIME_Y 2654435761u
#define PRIME_Z 805459861u

struct Params { int res[NLVL]; };

// ---------------- f32x2 packed helpers (sm_103a) ----------------
__device__ __forceinline__ unsigned long long pack2_f32(float lo, float hi) {
    unsigned long long r;
    asm("mov.b64 %0, {%1, %2};" : "=l"(r) : "r"(__float_as_uint(lo)), "r"(__float_as_uint(hi)));
    return r;
}
__device__ __forceinline__ unsigned long long fma_f32x2(unsigned long long a,
                                                        unsigned long long b,
                                                        unsigned long long c) {
    unsigned long long d;
    asm("fma.rn.f32x2 %0, %1, %2, %3;" : "=l"(d) : "l"(a), "l"(b), "l"(c));
    return d;
}
__device__ __forceinline__ float hsum_f32x2(unsigned long long v) {
    unsigned a, b;
    asm("mov.b64 {%0, %1}, %2;" : "=r"(a), "=r"(b) : "l"(v));
    return __uint_as_float(a) + __uint_as_float(b);
}
// named barrier over 128 threads (ids 1 and 2; warps never straddle halves)
__device__ __forceinline__ void half_bar(int id) {
    asm volatile("bar.sync %0, 128;" :: "r"(id) : "memory");
}

// ---- head: 4 points x 2 columns from a staged tile (proven R9 code) ----
__device__ __forceinline__ void head4(const float2 (*sEmb)[TILE_P], int pbase, int pg,
                                      int c0, int c1,
                                      const unsigned long long* w0,
                                      const unsigned long long* w1,
                                      unsigned long long b0, unsigned long long b1,
                                      float* __restrict__ out, int N)
{
    unsigned long long acc0[4] = {b0, b0, b0, b0};
    unsigned long long acc1[4] = {b1, b1, b1, b1};
#pragma unroll
    for (int l = 0; l < NLVL; ++l) {
        const ulonglong2 eA = *(const ulonglong2*)&sEmb[l][pg];
        const ulonglong2 eB = *(const ulonglong2*)&sEmb[l][pg + 2];
        acc0[0] = fma_f32x2(eA.x, w0[l], acc0[0]);
        acc1[0] = fma_f32x2(eA.x, w1[l], acc1[0]);
        acc0[1] = fma_f32x2(eA.y, w0[l], acc0[1]);
        acc1[1] = fma_f32x2(eA.y, w1[l], acc1[1]);
        acc0[2] = fma_f32x2(eB.x, w0[l], acc0[2]);
        acc1[2] = fma_f32x2(eB.x, w1[l], acc1[2]);
        acc0[3] = fma_f32x2(eB.y, w0[l], acc0[3]);
        acc1[3] = fma_f32x2(eB.y, w1[l], acc1[3]);
    }
#pragma unroll
    for (int i = 0; i < 4; ++i) {
        const int prow = pbase + pg + i;
        if (prow < N) {
            const size_t row = (size_t)prow * DOUT;
            __stcs(&out[row + c0], hsum_f32x2(acc0[i]));
            __stcs(&out[row + c1], hsum_f32x2(acc1[i]));
        }
    }
}

// ---- one hash-encode level, straight-line (proven R9 code) ----
__device__ __forceinline__ void gather_level(int l, float rs,
                                             float x, float y, float z,
                                             const float* __restrict__ tables,
                                             float2 (*sEmb)[TILE_P], int tid)
{
    const float px = x * rs, py = y * rs, pz = z * rs;
    const float fx = floorf(px), fy = floorf(py), fz = floorf(pz);
    const float tx = px - fx, ty = py - fy, tz = pz - fz;

    const unsigned ix = (unsigned)fx, iy = (unsigned)fy, iz = (unsigned)fz;
    const unsigned hy0 = iy * PRIME_Y, hy1 = hy0 + PRIME_Y;
    const unsigned hz0 = iz * PRIME_Z, hz1 = hz0 + PRIME_Z;

    const unsigned xm   = ix ^ (ix + 1u);
    const bool     oddx = (ix & 1u) != 0u;

    const unsigned q00 = (ix ^ hy0 ^ hz0) & TMASK;
    const unsigned q01 = (ix ^ hy0 ^ hz1) & TMASK;
    const unsigned q10 = (ix ^ hy1 ^ hz0) & TMASK;
    const unsigned q11 = (ix ^ hy1 ^ hz1) & TMASK;

    const float4* __restrict__ t4 = (const float4*)tables + (size_t)l * (TBL / 2);
    const float2* __restrict__ t2 = (const float2*)tables + (size_t)l * TBL;

    const float4 a00 = __ldg(t4 + (q00 >> 1));
    const float4 a01 = __ldg(t4 + (q01 >> 1));
    const float4 a10 = __ldg(t4 + (q10 >> 1));
    const float4 a11 = __ldg(t4 + (q11 >> 1));

    const float f000x = (q00 & 1) ? a00.z : a00.x, f000y = (q00 & 1) ? a00.w : a00.y;
    const float f001x = (q01 & 1) ? a01.z : a01.x, f001y = (q01 & 1) ? a01.w : a01.y;
    const float f010x = (q10 & 1) ? a10.z : a10.x, f010y = (q10 & 1) ? a10.w : a10.y;
    const float f011x = (q11 & 1) ? a11.z : a11.x, f011y = (q11 & 1) ? a11.w : a11.y;

    float f100x, f100y, f101x, f101y, f110x, f110y, f111x, f111y;
    if (oddx) {
        const float2 d00 = __ldg(t2 + ((q00 ^ xm) & TMASK));
        const float2 d01 = __ldg(t2 + ((q01 ^ xm) & TMASK));
        const float2 d10 = __ldg(t2 + ((q10 ^ xm) & TMASK));
        const float2 d11 = __ldg(t2 + ((q11 ^ xm) & TMASK));
        f100x = d00.x; f100y = d00.y;
        f101x = d01.x; f101y = d01.y;
        f110x = d10.x; f110y = d10.y;
        f111x = d11.x; f111y = d11.y;
    } else {
        f100x = (q00 & 1) ? a00.x : a00.z;  f100y = (q00 & 1) ? a00.y : a00.w;
        f101x = (q01 & 1) ? a01.x : a01.z;  f101y = (q01 & 1) ? a01.y : a01.w;
        f110x = (q10 & 1) ? a10.x : a10.z;  f110y = (q10 & 1) ? a10.y : a10.w;
        f111x = (q11 & 1) ? a11.x : a11.z;  f111y = (q11 & 1) ? a11.y : a11.w;
    }

    const float ux = 1.f - tx, uy = 1.f - ty, uz = 1.f - tz;
    const float a0 = ux * uy, a1 = ux * ty, a2 = tx * uy, a3 = tx * ty;
    const float w000 = a0 * uz, w001 = a0 * tz;
    const float w010 = a1 * uz, w011 = a1 * tz;
    const float w100 = a2 * uz, w101 = a2 * tz;
    const float w110 = a3 * uz, w111 = a3 * tz;

    float e0, e1;
    e0 = w000 * f000x;           e1 = w000 * f000y;
    e0 = fmaf(w001, f001x, e0);  e1 = fmaf(w001, f001y, e1);
    e0 = fmaf(w010, f010x, e0);  e1 = fmaf(w010, f010y, e1);
    e0 = fmaf(w011, f011x, e0);  e1 = fmaf(w011, f011y, e1);
    e0 = fmaf(w100, f100x, e0);  e1 = fmaf(w100, f100y, e1);
    e0 = fmaf(w101, f101x, e0);  e1 = fmaf(w101, f101y, e1);
    e0 = fmaf(w110, f110x, e0);  e1 = fmaf(w110, f110y, e1);
    e0 = fmaf(w111, f111x, e0);  e1 = fmaf(w111, f111y, e1);

    sEmb[l][tid] = make_float2(e0, e1);
}

__device__ __forceinline__ void epilogue256(const float2 (*sEmb)[TILE_P], int tid,
                                            int pbase,
                                            const float* __restrict__ W,
                                            const float* __restrict__ bias,
                                            float* __restrict__ out, int N)
{
    float acc = __ldg(&bias[256]);
#pragma unroll
    for (int l = 0; l < NLVL; ++l) {
        const float2 e = sEmb[l][tid];
        acc = fmaf(e.x, __ldg(&W[(2 * l) * DOUT + 256]), acc);
        acc = fmaf(e.y, __ldg(&W[(2 * l + 1) * DOUT + 256]), acc);
    }
    const int prow = pbase + tid;
    if (prow < N) __stcs(&out[(size_t)prow * DOUT + 256], acc);
}

__global__ __launch_bounds__(TPB, 2)
void hashsdf_kernel(const float* __restrict__ inputs,
                    const float* __restrict__ tables,
                    const float* __restrict__ W,
                    const float* __restrict__ bias,
                    float* __restrict__ out,
                    int N, int ntiles, Params prm)
{
    __shared__ __align__(16) float2 sA[NLVL][TILE_P];
    __shared__ __align__(16) float2 sB[NLVL][TILE_P];

    const int tid    = threadIdx.x;
    const int halfid = 1 + (tid >> 7);

    const int t0 = 2 * blockIdx.x;
    const int t1 = (t0 + 1 < ntiles) ? t0 + 1 : t0;   // degenerate: redo t0 (benign)
    const int pbase0 = t0 * TILE_P;
    const int pbase1 = t1 * TILE_P;

    // ---------------- gather tile t0 -> sA (unrolled, max MLP) ----------------
    {
        const int p = pbase0 + tid;
        float x = 0.f, y = 0.f, z = 0.f;
        if (p < N) { x = inputs[3 * p + 0]; y = inputs[3 * p + 1]; z = inputs[3 * p + 2]; }
#pragma unroll
        for (int l = 0; l < NLVL; ++l)
            gather_level(l, (float)prm.res[l], x, y, z, tables, sA, tid);
    }
    half_bar(halfid);

    // coords for t1 (issued early so they land before the merged loop needs them)
    float x1 = 0.f, y1 = 0.f, z1 = 0.f;
    {
        const int p = pbase1 + tid;
        if (p < N) { x1 = inputs[3 * p + 0]; y1 = inputs[3 * p + 1]; z1 = inputs[3 * p + 2]; }
    }

    // head setup: per-thread columns + packed weights (shared by both tiles)
    const int wid  = tid >> 5;
    const int lane = tid & 31;
    const int g    = wid & 3;
    const int h    = wid >> 2;
    const int c0   = g * 64 + lane;
    const int c1   = c0 + 32;

    unsigned long long w0[NLVL], w1[NLVL];
#pragma unroll
    for (int l = 0; l < NLVL; ++l) {
        w0[l] = pack2_f32(__ldg(&W[(2 * l) * DOUT + c0]), __ldg(&W[(2 * l + 1) * DOUT + c0]));
        w1[l] = pack2_f32(__ldg(&W[(2 * l) * DOUT + c1]), __ldg(&W[(2 * l + 1) * DOUT + c1]));
    }
    const unsigned long long b0 = pack2_f32(__ldg(&bias[c0]), 0.f);
    const unsigned long long b1 = pack2_f32(__ldg(&bias[c1]), 0.f);

    // ------- merged: gather t1 -> sB interleaved with head(t0) from sA -------
    // per level: issue t1 gathers, then 2-3 independent head chunks execute in
    // the load-latency shadow, then finish the level and store to sB.
    {
        int pg = h * 128;
        for (int u = 0; u < NLVL; ++u) {
            // gather is textually first: its LDGs issue before the head FMAs
            gather_level(u, (float)prm.res[u], x1, y1, z1, tables, sB, tid);
            const int nc = (u < 8) ? 3 : 2;           // 8*3 + 4*2 = 32 chunks
            for (int c = 0; c < nc; ++c) {
                head4(sA, pbase0, pg, c0, c1, w0, w1, b0, b1, out, N);
                pg += 4;
            }
        }
    }
    epilogue256(sA, tid, pbase0, W, bias, out, N);

    half_bar(halfid);

    // ---------------- head tile t1 from sB ----------------
    {
        const int pg_end = h * 128 + 128;
        for (int pg = h * 128; pg < pg_end; pg += 4)
            head4(sB, pbase1, pg, c0, c1, w0, w1, b0, b1, out, N);
    }
    epilogue256(sB, tid, pbase1, W, bias, out, N);
}

extern "C" void kernel_launch(void* const* d_in, const int* in_sizes, int n_in,
                              void* d_out, int out_size) {
    const float* inputs = (const float*)d_in[0];
    const float* tables = (const float*)d_in[1];
    const float* W      = (const float*)d_in[2];
    const float* bias   = (const float*)d_in[3];
    float* out          = (float*)d_out;

    const int N = in_sizes[0] / 3;

    // Replicate numpy's RES computation bit-exactly (RES[11] is analytically 2048;
    // floor outcome depends on libm rounding — do NOT hardcode).
    Params prm;
    const double growth = exp((log(2048.0) - log(16.0)) / 11.0);
    for (int l = 0; l < NLVL; ++l)
        prm.res[l] = (int)floor(16.0 * pow(growth, (double)l));

    const int ntiles = (N + TILE_P - 1) / TILE_P;
    const int grid   = (ntiles + 1) / 2;       // 2 tiles per block

    hashsdf_kernel<<<grid, TPB>>>(inputs, tables, W, bias, out, N, ntiles, prm);
}